// round 13
// baseline (speedup 1.0000x reference)
#include <cuda_runtime.h>

// StepRelu: y = 0 for x<=0; ((ceil(x/theta)-1)*theta) for 0<x<=theta*steps; x otherwise.
// theta = 0.1, steps = 16 -> upper = 1.6.
// R13: cache-hint ablation of the R12 optimum. Identical structure
// (128 thr, VEC=4 front-batched LDG.128, exact path) but DEFAULT load/store
// policy instead of __ldcs/__stcs — isolates whether streaming hints
// contribute anything at this working-set size (1 GiB >> 126 MB L2).

#define VEC 4        // float4s per thread
#define NTHREADS 128

__device__ __forceinline__ float step_relu(float x) {
    const float theta     = 0.1f;
    const float inv_theta = 10.0f;
    const float upper     = 1.6f;
    float binned = (ceilf(x * inv_theta) - 1.0f) * theta;
    float y = (x <= upper) ? binned : x;
    return (x <= 0.0f) ? 0.0f : y;
}

__device__ __forceinline__ float4 step_relu4(float4 v) {
    float4 r;
    r.x = step_relu(v.x);
    r.y = step_relu(v.y);
    r.z = step_relu(v.z);
    r.w = step_relu(v.w);
    return r;
}

// Fast path: n4 divisible by NTHREADS*VEC (512), no bounds checks.
__global__ void __launch_bounds__(NTHREADS) step_relu_v4x4_plain(
    const float4* __restrict__ in, float4* __restrict__ out)
{
    int base = blockIdx.x * (NTHREADS * VEC) + threadIdx.x;

    float4 v[VEC];
#pragma unroll
    for (int k = 0; k < VEC; k++)
        v[k] = in[base + k * NTHREADS];     // default policy, front-batched

#pragma unroll
    for (int k = 0; k < VEC; k++)
        out[base + k * NTHREADS] = step_relu4(v[k]);
}

// Generic guarded path (covers any n4 remainder region).
__global__ void __launch_bounds__(NTHREADS) step_relu_v4_guard(
    const float4* __restrict__ in, float4* __restrict__ out, int start, int n4)
{
    int i = start + blockIdx.x * blockDim.x + threadIdx.x;
    if (i < n4) out[i] = step_relu4(in[i]);
}

// Scalar tail for n % 4 != 0.
__global__ void step_relu_tail(
    const float* __restrict__ in, float* __restrict__ out, int start, int n)
{
    int i = start + blockIdx.x * blockDim.x + threadIdx.x;
    if (i < n) out[i] = step_relu(in[i]);
}

extern "C" void kernel_launch(void* const* d_in, const int* in_sizes, int n_in,
                              void* d_out, int out_size)
{
    const float* x = (const float*)d_in[0];
    float* y = (float*)d_out;
    int n = in_sizes[0];

    int n4 = n / 4;
    const int per_block = NTHREADS * VEC;     // 512 float4s per block
    int exact_blocks = n4 / per_block;

    if (exact_blocks > 0) {
        step_relu_v4x4_plain<<<exact_blocks, NTHREADS>>>(
            (const float4*)x, (float4*)y);
    }
    int done4 = exact_blocks * per_block;
    int rem4 = n4 - done4;
    if (rem4 > 0) {
        int blocks = (rem4 + NTHREADS - 1) / NTHREADS;
        step_relu_v4_guard<<<blocks, NTHREADS>>>(
            (const float4*)x, (float4*)y, done4, n4);
    }
    int rem = n - n4 * 4;
    if (rem > 0) {
        step_relu_tail<<<1, NTHREADS>>>(x, y, n4 * 4, n);
    }
}

// round 14
// speedup vs baseline: 1.0063x; 1.0063x over previous
#include <cuda_runtime.h>

// StepRelu: y = 0 for x<=0; ((ceil(x/theta)-1)*theta) for 0<x<=theta*steps; x otherwise.
// theta = 0.1, steps = 16 -> upper = 1.6.
// FINAL (R12 config, converged): 128-thread blocks, VEC=4 float4/thread,
// front-batched LDG.128 (MLP=4), __ldcs/__stcs streaming hints, zero-
// predication exact path, oversubscribed launch (65536 CTAs).
// Measured 85.8-86.6% of HBM spec (~6.8 TB/s) — the mixed r/w stream floor.
// Rejected by measurement: VEC=1 (72.5% DRAM, MLP-starved), VEC=8 (occ loss),
// __stwt (loses L2 write aggregation), default ld/st (L1 allocation burns
// wavefronts: 83.1% DRAM, L1 65.5%), persistent grid-stride (loop-carried
// register reuse collapses MLP: 73.3% DRAM).

#define VEC 4        // float4s per thread
#define NTHREADS 128

__device__ __forceinline__ float step_relu(float x) {
    const float theta     = 0.1f;
    const float inv_theta = 10.0f;
    const float upper     = 1.6f;
    float binned = (ceilf(x * inv_theta) - 1.0f) * theta;
    float y = (x <= upper) ? binned : x;
    return (x <= 0.0f) ? 0.0f : y;
}

__device__ __forceinline__ float4 step_relu4(float4 v) {
    float4 r;
    r.x = step_relu(v.x);
    r.y = step_relu(v.y);
    r.z = step_relu(v.z);
    r.w = step_relu(v.w);
    return r;
}

// Fast path: n4 divisible by NTHREADS*VEC (512), no bounds checks.
__global__ void __launch_bounds__(NTHREADS) step_relu_v4x4_128(
    const float4* __restrict__ in, float4* __restrict__ out)
{
    int base = blockIdx.x * (NTHREADS * VEC) + threadIdx.x;

    float4 v[VEC];
#pragma unroll
    for (int k = 0; k < VEC; k++)
        v[k] = __ldcs(in + base + k * NTHREADS);   // independent, front-batched

#pragma unroll
    for (int k = 0; k < VEC; k++)
        __stcs(out + base + k * NTHREADS, step_relu4(v[k]));
}

// Generic guarded path (covers any n4 remainder region).
__global__ void __launch_bounds__(NTHREADS) step_relu_v4_guard(
    const float4* __restrict__ in, float4* __restrict__ out, int start, int n4)
{
    int i = start + blockIdx.x * blockDim.x + threadIdx.x;
    if (i < n4) __stcs(out + i, step_relu4(__ldcs(in + i)));
}

// Scalar tail for n % 4 != 0.
__global__ void step_relu_tail(
    const float* __restrict__ in, float* __restrict__ out, int start, int n)
{
    int i = start + blockIdx.x * blockDim.x + threadIdx.x;
    if (i < n) out[i] = step_relu(in[i]);
}

extern "C" void kernel_launch(void* const* d_in, const int* in_sizes, int n_in,
                              void* d_out, int out_size)
{
    const float* x = (const float*)d_in[0];
    float* y = (float*)d_out;
    int n = in_sizes[0];

    int n4 = n / 4;
    const int per_block = NTHREADS * VEC;     // 512 float4s per block
    int exact_blocks = n4 / per_block;

    if (exact_blocks > 0) {
        step_relu_v4x4_128<<<exact_blocks, NTHREADS>>>(
            (const float4*)x, (float4*)y);
    }
    int done4 = exact_blocks * per_block;
    int rem4 = n4 - done4;
    if (rem4 > 0) {
        int blocks = (rem4 + NTHREADS - 1) / NTHREADS;
        step_relu_v4_guard<<<blocks, NTHREADS>>>(
            (const float4*)x, (float4*)y, done4, n4);
    }
    int rem = n - n4 * 4;
    if (rem > 0) {
        step_relu_tail<<<1, NTHREADS>>>(x, y, n4 * 4, n);
    }
}